// round 7
// baseline (speedup 1.0000x reference)
#include <cuda_runtime.h>
#include <cstdint>

#define DI __device__ __forceinline__

constexpr int D = 128, G = 8, F = 80, A = 18;
constexpr int BM = 128, THREADS = 256;

constexpr int HS  = 84;  // H stride (80 cols)   84 % 32 = 20 -> conflict-free frags
constexpr int WS  = 44;  // W2/3/4 half stride   44 % 32 = 12
constexpr int W1S = 36;  // W1 quarter stride    36 % 32 = 4
constexpr int SLOT = F * WS;  // 3520 floats per weight slot

constexpr int OFF_H  = 0;                 // 128*84 floats
constexpr int OFF_SW = BM * HS;           // 3 rotating weight slots
constexpr int OFF_SB = OFF_SW + 3 * SLOT; // b2(80) + b3(80)
constexpr int SMEM_FLOATS = OFF_SB + 2 * F;
constexpr int SMEM_BYTES  = SMEM_FLOATS * 4;  // 85888 B -> 2 CTAs/SM

// tf32 pre-rounded weight scratch
__device__ __align__(16) float g_W1r[G * F * D];
__device__ __align__(16) float g_W2r[F * F];
__device__ __align__(16) float g_W3r[F * F];
__device__ __align__(16) float g_W4r[G * A * F];

DI uint32_t tf32b(float x) {
    uint32_t r; asm("cvt.rna.tf32.f32 %0, %1;" : "=r"(r) : "f"(x));
    return r;
}
DI float tf32f(float x) { return __uint_as_float(tf32b(x)); }

DI void mma8(float* c, uint32_t a0, uint32_t a1, uint32_t a2, uint32_t a3,
             uint32_t b0, uint32_t b1) {
    asm("mma.sync.aligned.m16n8k8.row.col.f32.tf32.tf32.f32 "
        "{%0,%1,%2,%3}, {%4,%5,%6,%7}, {%8,%9}, {%0,%1,%2,%3};"
        : "+f"(c[0]), "+f"(c[1]), "+f"(c[2]), "+f"(c[3])
        : "r"(a0), "r"(a1), "r"(a2), "r"(a3), "r"(b0), "r"(b1));
}

DI void cpa16(uint32_t dst, const float* src) {
    asm volatile("cp.async.cg.shared.global [%0], [%1], 16;" :: "r"(dst), "l"(src));
}
#define CPA_COMMIT() asm volatile("cp.async.commit_group;" ::: "memory")
#define CPA_WAIT1()  asm volatile("cp.async.wait_group 1;" ::: "memory")

__global__ void prep_kernel(const float* __restrict__ W1, const float* __restrict__ W2,
                            const float* __restrict__ W3, const float* __restrict__ W4) {
    int i = blockIdx.x * blockDim.x + threadIdx.x;
    if (i < G * F * D) g_W1r[i] = tf32f(W1[i]);
    if (i < F * F) { g_W2r[i] = tf32f(W2[i]); g_W3r[i] = tf32f(W3[i]); }
    if (i < G * A * F) g_W4r[i] = tf32f(W4[i]);
}

// stage s -> prefetch its weights into slot s%3
DI void issue_stage(int s, int gLo, int nG, uint32_t swbase, int tid) {
    uint32_t dst0 = swbase + (uint32_t)(s % 3) * (SLOT * 4);
    if (s < 4 * nG) {                       // W1 quarter: 80 rows x 32 floats
        int g = gLo + (s >> 2), q = s & 3;
        const float* src = g_W1r + (size_t)g * F * D + q * 32;
        #pragma unroll
        for (int c = tid; c < 640; c += THREADS) {
            int n = c >> 3, cc = c & 7;
            cpa16(dst0 + n * (W1S * 4) + cc * 16, src + n * D + cc * 4);
        }
    } else {
        int t = s - 4 * nG;
        const float* src; int rows;
        if (t < 2)      { src = g_W2r + (t & 1) * 40; rows = F; }
        else if (t < 4) { src = g_W3r + (t & 1) * 40; rows = F; }
        else {
            int u = t - 4; int g = gLo + (u >> 1);
            src = g_W4r + (size_t)g * A * F + (u & 1) * 40; rows = A;
        }
        int nch = rows * 10;                // rows x 40 floats, stride WS
        for (int c = tid; c < nch; c += THREADS) {
            int n = c / 10, cc = c - n * 10;
            cpa16(dst0 + n * (WS * 4) + cc * 16, src + n * F + cc * 4);
        }
    }
}

__global__ __launch_bounds__(THREADS, 2)
void fused_kernel(const float* __restrict__ state, const int* __restrict__ idx,
                  const float* __restrict__ b1, const float* __restrict__ b2,
                  const float* __restrict__ b3, const float* __restrict__ b4,
                  float* __restrict__ out, int nTotal)
{
    extern __shared__ float sm[];
    float* H  = sm + OFF_H;
    float* sb = sm + OFF_SB;  // [0..79]=b2, [80..159]=b3

    uint32_t su;
    asm("{ .reg .u64 t; cvta.to.shared.u64 t, %1; cvt.u32.u64 %0, t; }"
        : "=r"(su) : "l"(sm));
    const uint32_t swbase = su + OFF_SW * 4;

    const int tid  = threadIdx.x;
    const int lane = tid & 31;
    const int wid  = tid >> 5;
    const int gid  = lane >> 2;
    const int tig  = lane & 3;

    // 4 m-warps x 2 n-warps; each warp: 2 m16 tiles x 5 n-tiles
    const int mw = wid & 3;
    const int nw = wid >> 2;
    const int nbase = nw * 40;
    const int rA0 = mw * 32 + gid;        // t=0: rows rA0, rA0+8
    const int rA1 = mw * 32 + 16 + gid;   // t=1: rows rA1, rA1+8

    const int mBase  = blockIdx.x * BM;
    const int nValid = min(BM, nTotal - mBase);

    const int gLo = __ldg(&idx[mBase]);
    const int gHi = __ldg(&idx[mBase + nValid - 1]);
    const int nG = gHi - gLo + 1;
    const int nStages = 6 * nG + 4;

    int mg[2][2];
    mg[0][0] = (rA0     < nValid) ? __ldg(&idx[mBase + rA0])      : -1;
    mg[0][1] = (rA0 + 8 < nValid) ? __ldg(&idx[mBase + rA0 + 8])  : -1;
    mg[1][0] = (rA1     < nValid) ? __ldg(&idx[mBase + rA1])      : -1;
    mg[1][1] = (rA1 + 8 < nValid) ? __ldg(&idx[mBase + rA1 + 8])  : -1;

    if (tid < 2 * F) sb[tid] = (tid < F) ? b2[tid] : b3[tid - F];

    // clamped state row pointers (t, half)
    const float* sp[2][2];
    sp[0][0] = state + (size_t)min(mBase + rA0,     nTotal - 1) * D;
    sp[0][1] = state + (size_t)min(mBase + rA0 + 8, nTotal - 1) * D;
    sp[1][0] = state + (size_t)min(mBase + rA1,     nTotal - 1) * D;
    sp[1][1] = state + (size_t)min(mBase + rA1 + 8, nTotal - 1) * D;

    issue_stage(0, gLo, nG, swbase, tid); CPA_COMMIT();
    issue_stage(1, gLo, nG, swbase, tid); CPA_COMMIT();

    float acc[2][5][4];

    for (int s = 0; s < nStages; ++s) {
        CPA_WAIT1();
        __syncthreads();
        const float* SWp = sm + OFF_SW + (s % 3) * SLOT;

        if (s < 4 * nG) {
            // ---------- Layer 1, quarter q of game g ----------
            int g = gLo + (s >> 2), q = s & 3;
            if (q == 0) {
                #pragma unroll
                for (int t = 0; t < 2; ++t)
                    #pragma unroll
                    for (int nt = 0; nt < 5; ++nt)
                        #pragma unroll
                        for (int i = 0; i < 4; ++i) acc[t][nt][i] = 0.f;
            }
            #pragma unroll
            for (int kl = 0; kl < 4; ++kl) {
                int kb = q * 32 + kl * 8;
                uint32_t af[2][4];
                #pragma unroll
                for (int t = 0; t < 2; ++t) {
                    af[t][0] = tf32b(__ldg(sp[t][0] + kb + tig));
                    af[t][1] = tf32b(__ldg(sp[t][1] + kb + tig));
                    af[t][2] = tf32b(__ldg(sp[t][0] + kb + tig + 4));
                    af[t][3] = tf32b(__ldg(sp[t][1] + kb + tig + 4));
                }
                #pragma unroll
                for (int nt = 0; nt < 5; ++nt) {
                    const float* bp = SWp + (nbase + nt * 8 + gid) * W1S + kl * 8 + tig;
                    uint32_t b0 = __float_as_uint(bp[0]);
                    uint32_t bv = __float_as_uint(bp[4]);
                    mma8(acc[0][nt], af[0][0], af[0][1], af[0][2], af[0][3], b0, bv);
                    mma8(acc[1][nt], af[1][0], af[1][1], af[1][2], af[1][3], b0, bv);
                }
            }
            if (q == 3) {  // masked epilogue -> H (tf32-rounded)
                #pragma unroll
                for (int t = 0; t < 2; ++t) {
                    int rr = (t == 0) ? rA0 : rA1;
                    #pragma unroll
                    for (int hf = 0; hf < 2; ++hf) {
                        if (mg[t][hf] == g) {
                            int row = rr + hf * 8;
                            #pragma unroll
                            for (int nt = 0; nt < 5; ++nt) {
                                int c = nbase + nt * 8 + 2 * tig;
                                float2 w = make_float2(
                                    tf32f(fmaxf(acc[t][nt][2 * hf]     + __ldg(&b1[g * F + c]),     0.f)),
                                    tf32f(fmaxf(acc[t][nt][2 * hf + 1] + __ldg(&b1[g * F + c + 1]), 0.f)));
                                *(float2*)(H + row * HS + c) = w;
                            }
                        }
                    }
                }
            }
        } else if (s - 4 * nG < 4) {
            // ---------- Layers 2 & 3, half h ----------
            int t4 = s - 4 * nG;
            int l = t4 >> 1, h = t4 & 1;
            if (h == 0) {
                #pragma unroll
                for (int t = 0; t < 2; ++t)
                    #pragma unroll
                    for (int nt = 0; nt < 5; ++nt)
                        #pragma unroll
                        for (int i = 0; i < 4; ++i) acc[t][nt][i] = 0.f;
            }
            #pragma unroll
            for (int kl = 0; kl < 5; ++kl) {
                int kb = h * 40 + kl * 8;
                uint32_t af[2][4];
                af[0][0] = __float_as_uint(H[rA0 * HS + kb + tig]);
                af[0][1] = __float_as_uint(H[(rA0 + 8) * HS + kb + tig]);
                af[0][2] = __float_as_uint(H[rA0 * HS + kb + tig + 4]);
                af[0][3] = __float_as_uint(H[(rA0 + 8) * HS + kb + tig + 4]);
                af[1][0] = __float_as_uint(H[rA1 * HS + kb + tig]);
                af[1][1] = __float_as_uint(H[(rA1 + 8) * HS + kb + tig]);
                af[1][2] = __float_as_uint(H[rA1 * HS + kb + tig + 4]);
                af[1][3] = __float_as_uint(H[(rA1 + 8) * HS + kb + tig + 4]);
                #pragma unroll
                for (int nt = 0; nt < 5; ++nt) {
                    const float* bp = SWp + (nbase + nt * 8 + gid) * WS + kl * 8 + tig;
                    uint32_t b0 = __float_as_uint(bp[0]);
                    uint32_t bv = __float_as_uint(bp[4]);
                    mma8(acc[0][nt], af[0][0], af[0][1], af[0][2], af[0][3], b0, bv);
                    mma8(acc[1][nt], af[1][0], af[1][1], af[1][2], af[1][3], b0, bv);
                }
            }
            if (h == 1) {  // in-place epilogue (warp-private rows x its 40 cols)
                #pragma unroll
                for (int t = 0; t < 2; ++t) {
                    int rr = (t == 0) ? rA0 : rA1;
                    #pragma unroll
                    for (int nt = 0; nt < 5; ++nt) {
                        int c = nbase + nt * 8 + 2 * tig;
                        float2 w0 = make_float2(
                            tf32f(fmaxf(acc[t][nt][0] + sb[l * F + c], 0.f)),
                            tf32f(fmaxf(acc[t][nt][1] + sb[l * F + c + 1], 0.f)));
                        float2 w1 = make_float2(
                            tf32f(fmaxf(acc[t][nt][2] + sb[l * F + c], 0.f)),
                            tf32f(fmaxf(acc[t][nt][3] + sb[l * F + c + 1], 0.f)));
                        *(float2*)(H + rr * HS + c) = w0;
                        *(float2*)(H + (rr + 8) * HS + c) = w1;
                    }
                }
            }
        } else {
            // ---------- Layer 4, half h of game g ----------
            int u = s - 4 * nG - 4;
            int g = gLo + (u >> 1), h = u & 1;
            const int nT4 = (nw == 0) ? 2 : 1;   // nw0 -> nt {0,1}, nw1 -> nt {2}
            if (h == 0) {
                #pragma unroll
                for (int t = 0; t < 2; ++t)
                    #pragma unroll
                    for (int i = 0; i < 2; ++i)
                        #pragma unroll
                        for (int q2 = 0; q2 < 4; ++q2) acc[t][i][q2] = 0.f;
            }
            #pragma unroll
            for (int kl = 0; kl < 5; ++kl) {
                int kb = h * 40 + kl * 8;
                uint32_t af[2][4];
                af[0][0] = __float_as_uint(H[rA0 * HS + kb + tig]);
                af[0][1] = __float_as_uint(H[(rA0 + 8) * HS + kb + tig]);
                af[0][2] = __float_as_uint(H[rA0 * HS + kb + tig + 4]);
                af[0][3] = __float_as_uint(H[(rA0 + 8) * HS + kb + tig + 4]);
                af[1][0] = __float_as_uint(H[rA1 * HS + kb + tig]);
                af[1][1] = __float_as_uint(H[(rA1 + 8) * HS + kb + tig]);
                af[1][2] = __float_as_uint(H[rA1 * HS + kb + tig + 4]);
                af[1][3] = __float_as_uint(H[(rA1 + 8) * HS + kb + tig + 4]);
                #pragma unroll
                for (int i = 0; i < 2; ++i) {
                    if (i < nT4) {
                        int ntG = nw * 2 + i;
                        // B rows >= 18 hold stale finite data; outputs masked below
                        const float* bp = SWp + (ntG * 8 + gid) * WS + kl * 8 + tig;
                        uint32_t b0 = __float_as_uint(bp[0]);
                        uint32_t bv = __float_as_uint(bp[4]);
                        mma8(acc[0][i], af[0][0], af[0][1], af[0][2], af[0][3], b0, bv);
                        mma8(acc[1][i], af[1][0], af[1][1], af[1][2], af[1][3], b0, bv);
                    }
                }
            }
            if (h == 1) {
                #pragma unroll
                for (int i = 0; i < 2; ++i) {
                    if (i < nT4) {
                        int ntG = nw * 2 + i;
                        int c = ntG * 8 + 2 * tig;
                        if (c < A) {
                            float bb0 = __ldg(&b4[g * A + c]);
                            float bb1 = __ldg(&b4[g * A + c + 1]);
                            #pragma unroll
                            for (int t = 0; t < 2; ++t) {
                                int rr = (t == 0) ? rA0 : rA1;
                                if (mg[t][0] == g) {
                                    float2 v = make_float2(acc[t][i][0] + bb0, acc[t][i][1] + bb1);
                                    *(float2*)(out + (size_t)(mBase + rr) * A + c) = v;
                                }
                                if (mg[t][1] == g) {
                                    float2 v = make_float2(acc[t][i][2] + bb0, acc[t][i][3] + bb1);
                                    *(float2*)(out + (size_t)(mBase + rr + 8) * A + c) = v;
                                }
                            }
                        }
                    }
                }
            }
        }

        if (s + 2 < nStages) issue_stage(s + 2, gLo, nG, swbase, tid);
        CPA_COMMIT();
    }
}

extern "C" void kernel_launch(void* const* d_in, const int* in_sizes, int n_in,
                              void* d_out, int out_size) {
    const float* state = (const float*)d_in[0];
    const int*   idx   = (const int*)d_in[1];
    const float* W1    = (const float*)d_in[2];
    const float* b1    = (const float*)d_in[3];
    const float* W2    = (const float*)d_in[4];
    const float* b2    = (const float*)d_in[5];
    const float* W3    = (const float*)d_in[6];
    const float* b3    = (const float*)d_in[7];
    const float* W4    = (const float*)d_in[8];
    const float* b4    = (const float*)d_in[9];
    float* out = (float*)d_out;

    const int B = in_sizes[1];

    prep_kernel<<<(G * F * D + 255) / 256, 256>>>(W1, W2, W3, W4);

    cudaFuncSetAttribute(fused_kernel, cudaFuncAttributeMaxDynamicSharedMemorySize, SMEM_BYTES);
    int grid = (B + BM - 1) / BM;
    fused_kernel<<<grid, THREADS, SMEM_BYTES>>>(state, idx, b1, b2, b3, b4, out, B);
}